// round 16
// baseline (speedup 1.0000x reference)
#include <cuda_runtime.h>
#include <cuda_fp16.h>
#include <math.h>
#include <stdint.h>

#define NU 100000
#define NI 50000
#define KN 100
#define BB 8192

// Precomputed fp16 tables
__device__ __half g_pe_user[NU * 64];
__device__ __half g_pe_item[NI * 64];
__device__ __half g_uscr16[(size_t)NU * 112];
__device__ __half g_iscr16[(size_t)NI * 112];
__device__ __half g_w2h[64 * 64];
__device__ __half g_w3h[32 * 64];
__device__ __half g_w4h[32 * 32];
__device__ __half g_b2h[64];
__device__ __half g_b3h[32];
__device__ __half g_b4h[32];

// ---------------------------------------------------------------------------
// Main-kernel SMEM, 3 CTAs/SM. Activations never touch smem (register chain).
//   ABUF [112 r][120 kh] stride 240B @ 0 (26880)
//   B1  [224 k][64 nh] stride 128B XOR-swizzled @ 26880 (28672)
//   W2 [64][72h] stride 144 @ 55552 (9216)
//   W3 [32][72h] stride 144 @ 64768 (4608)
//   W4 [32][40h] stride 80  @ 69376 (2560)
//   MISC (floats)           @ 71936
// ---------------------------------------------------------------------------
#define OFF_AB   0
#define OFF_B1   26880
#define OFF_W2   55552
#define OFF_W3   64768
#define OFF_W4   69376
#define OFF_MISC 71936
#define SMEM_BYTES 73792
#define MISC_W5   0
#define MISC_B5   32
#define MISC_RED  36
#define MISC_NIDX 152

#define PERSIST_GRID 444   // 148 SMs x 3 CTAs

#define CP_ASYNC16(dst, src) \
    asm volatile("cp.async.cg.shared.global [%0], [%1], 16;" :: "r"(dst), "l"(src))
#define CP_COMMIT() asm volatile("cp.async.commit_group;" ::: "memory")
#define CP_WAIT0()  asm volatile("cp.async.wait_group 0;" ::: "memory")

__device__ __forceinline__ void ldsm4(uint32_t (&r)[4], uint32_t a) {
    asm volatile("ldmatrix.sync.aligned.m8n8.x4.shared.b16 {%0,%1,%2,%3}, [%4];"
                 : "=r"(r[0]), "=r"(r[1]), "=r"(r[2]), "=r"(r[3]) : "r"(a));
}
__device__ __forceinline__ void ldsm2(uint32_t (&r)[2], uint32_t a) {
    asm volatile("ldmatrix.sync.aligned.m8n8.x2.shared.b16 {%0,%1}, [%2];"
                 : "=r"(r[0]), "=r"(r[1]) : "r"(a));
}
__device__ __forceinline__ void ldsm4t(uint32_t (&r)[4], uint32_t a) {
    asm volatile("ldmatrix.sync.aligned.m8n8.x4.trans.shared.b16 {%0,%1,%2,%3}, [%4];"
                 : "=r"(r[0]), "=r"(r[1]), "=r"(r[2]), "=r"(r[3]) : "r"(a));
}
__device__ __forceinline__ void mma_f32acc(float (&c)[4], const uint32_t* a,
                                           const uint32_t* b) {
    asm volatile(
        "mma.sync.aligned.m16n8k16.row.col.f32.f16.f16.f32 "
        "{%0,%1,%2,%3}, {%4,%5,%6,%7}, {%8,%9}, {%0,%1,%2,%3};"
        : "+f"(c[0]), "+f"(c[1]), "+f"(c[2]), "+f"(c[3])
        : "r"(a[0]), "r"(a[1]), "r"(a[2]), "r"(a[3]), "r"(b[0]), "r"(b[1]));
}
__device__ __forceinline__ void mma_f16acc(uint32_t (&c)[2], const uint32_t* a,
                                           const uint32_t* b) {
    asm volatile(
        "mma.sync.aligned.m16n8k16.row.col.f16.f16.f16.f16 "
        "{%0,%1}, {%2,%3,%4,%5}, {%6,%7}, {%0,%1};"
        : "+r"(c[0]), "+r"(c[1])
        : "r"(a[0]), "r"(a[1]), "r"(a[2]), "r"(a[3]), "r"(b[0]), "r"(b[1]));
}

__device__ __forceinline__ uint32_t h2_bits(float x, float y) {
    __half2 h = __floats2half2_rn(x, y);
    return *(uint32_t*)&h;
}
__device__ __forceinline__ void cvt_store4(char* dst, float4 v) {
    uint32_t lo = h2_bits(v.x, v.y), hi = h2_bits(v.z, v.w);
    uint2 u; u.x = lo; u.y = hi;
    *(uint2*)dst = u;
}

// ---------------------------------------------------------------------------
// scrpre_kernel (NO smem -> full occupancy): scr u/i conversion + wcvt
// ---------------------------------------------------------------------------
#define SCRU_BLK ((NU * 14 + 255) / 256)
#define SCRI_BLK ((NI * 14 + 255) / 256)
#define WCVT_BLK 29
#define SCRPRE_BLOCKS (SCRU_BLK + SCRI_BLK + WCVT_BLK)

__device__ __forceinline__ void scr_chunk(
    const float* __restrict__ src, __half* __restrict__ dst, int nrows, int t)
{
    if (t >= nrows * 14) return;
    int n = t / 14, cb = t % 14;
    uint32_t o[4] = {0, 0, 0, 0};
    if (cb < 12) {
        float4 a = *(const float4*)(src + (size_t)n * 100 + cb * 8);
        float4 bq = *(const float4*)(src + (size_t)n * 100 + cb * 8 + 4);
        o[0] = h2_bits(a.x, a.y);  o[1] = h2_bits(a.z, a.w);
        o[2] = h2_bits(bq.x, bq.y); o[3] = h2_bits(bq.z, bq.w);
    } else if (cb == 12) {
        float4 a = *(const float4*)(src + (size_t)n * 100 + 96);
        o[0] = h2_bits(a.x, a.y);  o[1] = h2_bits(a.z, a.w);
    }
    uint4 v; v.x = o[0]; v.y = o[1]; v.z = o[2]; v.w = o[3];
    *(uint4*)(dst + (size_t)n * 112 + cb * 8) = v;
}

__global__ __launch_bounds__(256) void scrpre_kernel(
    const float* __restrict__ user_scr, const float* __restrict__ item_scr,
    const float* __restrict__ w2, const float* __restrict__ w3,
    const float* __restrict__ w4, const float* __restrict__ b2,
    const float* __restrict__ b3, const float* __restrict__ b4)
{
    const int bid = blockIdx.x, tid = threadIdx.x;
    if (bid < SCRU_BLK) {
        scr_chunk(user_scr, g_uscr16, NU, bid * 256 + tid);
    } else if (bid < SCRU_BLK + SCRI_BLK) {
        scr_chunk(item_scr, g_iscr16, NI, (bid - SCRU_BLK) * 256 + tid);
    } else {
        int t = (bid - SCRU_BLK - SCRI_BLK) * 256 + tid;
        if (t < 4096) g_w2h[t] = __float2half_rn(w2[t]);
        else if (t < 6144) g_w3h[t - 4096] = __float2half_rn(w3[t - 4096]);
        else if (t < 7168) g_w4h[t - 6144] = __float2half_rn(w4[t - 6144]);
        else if (t < 7232) g_b2h[t - 7168] = __float2half_rn(b2[t - 7168]);
        else if (t < 7264) g_b3h[t - 7232] = __float2half_rn(b3[t - 7232]);
        else if (t < 7296) g_b4h[t - 7264] = __float2half_rn(b4[t - 7264]);
    }
}

// ---------------------------------------------------------------------------
// pe_kernel (smem; separate launch)
// ---------------------------------------------------------------------------
#define PEU_BLOCKS  ((NU + 255) / 256)
#define PEI_BLOCKS  ((NI + 255) / 256)
#define PE_BLOCKS   (PEU_BLOCKS + PEI_BLOCKS)

__device__ __forceinline__ void pe_block(
    const float* __restrict__ emb, const float* __restrict__ w1,
    int w1_off, __half* __restrict__ pe, int nrows, int rows0,
    __half* W1h, __half* E, int tid)
{
    for (int t = tid; t < 64 * 16; t += 256) {
        int o = t >> 4, k4 = t & 15;
        float4 v = *(const float4*)(w1 + o * 128 + w1_off + k4 * 4);
        cvt_store4((char*)(W1h + o * 72 + k4 * 4), v);
    }
    for (int t = tid; t < 256 * 16; t += 256) {
        int r = t >> 4, k4 = t & 15;
        int n = rows0 + r;
        float4 v = (n < nrows) ? *(const float4*)(emb + (size_t)n * 64 + k4 * 4)
                               : make_float4(0.f, 0.f, 0.f, 0.f);
        cvt_store4((char*)(E + r * 72 + k4 * 4), v);
    }
    __syncthreads();

    const int lane = tid & 31, w = tid >> 5;
    uint32_t sE = (uint32_t)__cvta_generic_to_shared(E);
    uint32_t sW = (uint32_t)__cvta_generic_to_shared(W1h);
    uint32_t aAddr[2];
#pragma unroll
    for (int mt = 0; mt < 2; mt++)
        aAddr[mt] = sE + (uint32_t)(w * 32 + mt * 16 + (lane & 15)) * 144u
                  + (uint32_t)((lane >> 4) << 4);
    uint32_t bAddr0 = sW + (uint32_t)(lane & 7) * 144u + (uint32_t)(((lane >> 3) & 1) << 4);

    float acc[2][8][4];
#pragma unroll
    for (int mt = 0; mt < 2; mt++)
#pragma unroll
        for (int nt = 0; nt < 8; nt++)
#pragma unroll
            for (int i = 0; i < 4; i++) acc[mt][nt][i] = 0.f;

#pragma unroll
    for (int ks = 0; ks < 4; ks++) {
        uint32_t a[2][4];
        ldsm4(a[0], aAddr[0] + ks * 32);
        ldsm4(a[1], aAddr[1] + ks * 32);
#pragma unroll
        for (int nt = 0; nt < 8; nt++) {
            uint32_t b[2];
            ldsm2(b, bAddr0 + (uint32_t)nt * 8u * 144u + ks * 32);
            mma_f32acc(acc[0][nt], a[0], b);
            mma_f32acc(acc[1][nt], a[1], b);
        }
    }

    int c0 = (lane & 3) * 2;
#pragma unroll
    for (int mt = 0; mt < 2; mt++) {
        int r0 = rows0 + w * 32 + mt * 16 + (lane >> 2);
#pragma unroll
        for (int nt = 0; nt < 8; nt++) {
            int col = nt * 8 + c0;
            if (r0 < nrows)
                *(__half2*)(pe + (size_t)r0 * 64 + col) =
                    __floats2half2_rn(acc[mt][nt][0], acc[mt][nt][1]);
            if (r0 + 8 < nrows)
                *(__half2*)(pe + (size_t)(r0 + 8) * 64 + col) =
                    __floats2half2_rn(acc[mt][nt][2], acc[mt][nt][3]);
        }
    }
}

__global__ __launch_bounds__(256) void pe_kernel(
    const float* __restrict__ user_emb, const float* __restrict__ item_emb,
    const float* __restrict__ w1)
{
    __shared__ __half W1h[64 * 72];
    __shared__ __half E[256 * 72];
    const int bid = blockIdx.x, tid = threadIdx.x;
    if (bid < PEU_BLOCKS)
        pe_block(user_emb, w1, 0, g_pe_user, NU, bid * 256, W1h, E, tid);
    else
        pe_block(item_emb, w1, 64, g_pe_item, NI, (bid - PEU_BLOCKS) * 256, W1h, E, tid);
}

// ---------------------------------------------------------------------------
// Persistent main kernel: grid=444; each CTA loops over batch elements with
// stride gridDim. Weights/pads/w5 loaded ONCE; per-iteration only the gathers.
// Warp weff (0-6) owns rows 16*weff..+15; MLP chain after GEMM1 in registers.
// ---------------------------------------------------------------------------
__global__ __launch_bounds__(256, 3) void cnn_main_kernel(
    const float* __restrict__ b1g,
    const float* __restrict__ w5g, const float* __restrict__ b5g,
    const int* __restrict__ uidxT, const int* __restrict__ iidxT,
    const int* __restrict__ uidxs, const int* __restrict__ iidxs,
    float* __restrict__ out)
{
    extern __shared__ char smb[];
    float* misc = (float*)(smb + OFF_MISC);
    int* nidx = (int*)(misc + MISC_NIDX);
    uint32_t sbase = (uint32_t)__cvta_generic_to_shared(smb);
    const int tid = threadIdx.x;
    const int lane = tid & 31, w = tid >> 5;
    const int cc = (lane & 3) * 2;
    const int r = lane >> 2;

    // ---------------- One-time setup ----------------
    if (tid < 32) misc[MISC_W5 + tid] = w5g[tid];
    else if (tid == 32) misc[MISC_B5] = b5g[0];
    if (tid < 192) {
        int rr = tid >> 3;
        int row = (rr < 12) ? 100 + rr : 200 + rr;
        *(uint4*)(smb + OFF_B1 + row * 128 + (tid & 7) * 16) = make_uint4(0, 0, 0, 0);
    }
    for (int t = tid; t < 512; t += 256) {
        int o = t >> 3, c = t & 7;
        CP_ASYNC16(sbase + OFF_W2 + (uint32_t)(o * 144 + c * 16),
                   (const char*)(g_w2h + o * 64 + c * 8));
    }
    if (tid < 256) {
        int o = tid >> 3, c = tid & 7;
        CP_ASYNC16(sbase + OFF_W3 + (uint32_t)(o * 144 + c * 16),
                   (const char*)(g_w3h + o * 64 + c * 8));
    }
    if (tid < 128) {
        int o = tid >> 2, c = tid & 3;
        CP_ASYNC16(sbase + OFF_W4 + (uint32_t)(o * 80 + c * 16),
                   (const char*)(g_w4h + o * 32 + c * 8));
    }
    CP_COMMIT();
    CP_WAIT0();
    __syncthreads();

    // ---------------- Batch loop ----------------
    for (int b = blockIdx.x; b < BB; b += PERSIST_GRID) {
        if (tid < 200) {
            nidx[tid] = (tid < 100) ? uidxT[(size_t)uidxs[b] * KN + tid]
                                    : iidxT[(size_t)iidxs[b] * KN + (tid - 100)];
        }
        __syncthreads();   // nidx visible; prior iter's smem reads all done

        // Gathers: ABUF user halves + B1 pe rows
        for (int t = tid; t < 1400; t += 256) {
            int rr = t / 14, c = t % 14;
            CP_ASYNC16(sbase + OFF_AB + (uint32_t)(rr * 240 + c * 16),
                       (const char*)(g_uscr16 + (size_t)nidx[rr] * 112) + c * 16);
        }
        for (int t = tid; t < 1600; t += 256) {
            int j = t >> 3, c = t & 7;
            const char* src = (j < 100)
                ? (const char*)(g_pe_user + (size_t)nidx[j] * 64) + c * 16
                : (const char*)(g_pe_item + (size_t)nidx[j] * 64) + c * 16;
            int dr = (j < 100) ? j : j + 12;
            CP_ASYNC16(sbase + OFF_B1 + (uint32_t)(dr * 128 + ((c ^ (dr & 7)) << 4)), src);
        }
        CP_COMMIT();
        CP_WAIT0();
        __syncthreads();   // tiles resident

        const int weff = (w + b) & 7;   // rotate idle warp per batch element

        if (weff < 7) {
            // ---- GEMM1 (fp32 acc): rows 16*weff.., 8 n-tiles, K=224 (2x7)
            float acc1[8][4];
#pragma unroll
            for (int t = 0; t < 8; t++)
#pragma unroll
                for (int i = 0; i < 4; i++) acc1[t][i] = 0.f;

            uint32_t aAddr = sbase + OFF_AB
                           + (uint32_t)(weff * 16 + (lane & 15)) * 240u
                           + (uint32_t)((lane >> 4) << 4);
            uint32_t bAddr[4];
#pragma unroll
            for (int j = 0; j < 4; j++)
                bAddr[j] = sbase + OFF_B1 + (uint32_t)(lane & 15) * 128u
                         + (uint32_t)((((j * 2 + (lane >> 4)) ^ (lane & 7)) & 7) << 4);

#pragma unroll
            for (int ks = 0; ks < 7; ks++) {
                uint32_t a[4];
                ldsm4(a, aAddr + ks * 32);
#pragma unroll
                for (int j = 0; j < 4; j++) {
                    uint32_t bq[4];
                    ldsm4t(bq, bAddr[j] + ks * 2048);
                    mma_f32acc(acc1[j * 2], a, &bq[0]);
                    mma_f32acc(acc1[j * 2 + 1], a, &bq[2]);
                }
            }

            // warp-local reload: item scr halves into own 16 ABUF rows
            for (int t = lane; t < 224; t += 32) {
                int rl = t / 14, c = t % 14;
                int rr = weff * 16 + rl;
                if (rr < 100)
                    CP_ASYNC16(sbase + OFF_AB + (uint32_t)(rr * 240 + c * 16),
                               (const char*)(g_iscr16 + (size_t)nidx[100 + rr] * 112) + c * 16);
            }
            CP_COMMIT();
            CP_WAIT0();
            __syncwarp();

#pragma unroll
            for (int ks = 0; ks < 7; ks++) {
                uint32_t a[4];
                ldsm4(a, aAddr + ks * 32);
#pragma unroll
                for (int j = 0; j < 4; j++) {
                    uint32_t bq[4];
                    ldsm4t(bq, bAddr[j] + 14336 + ks * 2048);
                    mma_f32acc(acc1[j * 2], a, &bq[0]);
                    mma_f32acc(acc1[j * 2 + 1], a, &bq[2]);
                }
            }

            // Epilogue 1 (regs): relu(+b1) -> L2 A-fragments
            uint32_t af[4][4];
#pragma unroll
            for (int t = 0; t < 8; t++) {
                float2 bf = *(const float2*)(b1g + t * 8 + cc);
                uint32_t u0 = h2_bits(fmaxf(acc1[t][0] + bf.x, 0.f),
                                      fmaxf(acc1[t][1] + bf.y, 0.f));
                uint32_t u1 = h2_bits(fmaxf(acc1[t][2] + bf.x, 0.f),
                                      fmaxf(acc1[t][3] + bf.y, 0.f));
                af[t >> 1][(t & 1) * 2 + 0] = u0;
                af[t >> 1][(t & 1) * 2 + 1] = u1;
            }

            const __half2 z = __floats2half2_rn(0.f, 0.f);

            // ---- L2 (f16 acc): K=64, N=64 ----
            uint32_t acc2[8][2];
#pragma unroll
            for (int t = 0; t < 8; t++) { acc2[t][0] = 0u; acc2[t][1] = 0u; }
            {
                uint32_t wA[4];
#pragma unroll
                for (int j = 0; j < 4; j++)
                    wA[j] = sbase + OFF_W2
                          + (uint32_t)((j * 2 + (lane >> 4)) * 8 + (lane & 7)) * 144u
                          + (uint32_t)(((lane >> 3) & 1) << 4);
#pragma unroll
                for (int ks = 0; ks < 4; ks++) {
#pragma unroll
                    for (int j = 0; j < 4; j++) {
                        uint32_t bw[4];
                        ldsm4(bw, wA[j] + ks * 32);
                        mma_f16acc(acc2[j * 2], af[ks], &bw[0]);
                        mma_f16acc(acc2[j * 2 + 1], af[ks], &bw[2]);
                    }
                }
            }
            // Epilogue 2 (regs): relu(+b2) -> L3 A-frags (reuse af)
            uint32_t af2[2][4];
#pragma unroll
            for (int t = 0; t < 8; t++) {
                __half2 b2v = *(const __half2*)(g_b2h + t * 8 + cc);
                __half2 v0 = __hmax2(__hadd2(*(__half2*)&acc2[t][0], b2v), z);
                __half2 v1 = __hmax2(__hadd2(*(__half2*)&acc2[t][1], b2v), z);
                af[t >> 1][(t & 1) * 2 + 0] = *(uint32_t*)&v0;
                af[t >> 1][(t & 1) * 2 + 1] = *(uint32_t*)&v1;
            }

            // ---- L3 (f16 acc): K=64, N=32 ----
            uint32_t acc3[4][2];
#pragma unroll
            for (int t = 0; t < 4; t++) { acc3[t][0] = 0u; acc3[t][1] = 0u; }
            {
                uint32_t wA[2];
#pragma unroll
                for (int j = 0; j < 2; j++)
                    wA[j] = sbase + OFF_W3
                          + (uint32_t)((j * 2 + (lane >> 4)) * 8 + (lane & 7)) * 144u
                          + (uint32_t)(((lane >> 3) & 1) << 4);
#pragma unroll
                for (int ks = 0; ks < 4; ks++) {
#pragma unroll
                    for (int j = 0; j < 2; j++) {
                        uint32_t bw[4];
                        ldsm4(bw, wA[j] + ks * 32);
                        mma_f16acc(acc3[j * 2], af[ks], &bw[0]);
                        mma_f16acc(acc3[j * 2 + 1], af[ks], &bw[2]);
                    }
                }
            }
            // Epilogue 3 (regs): relu(+b3) -> L4 A-frags
#pragma unroll
            for (int t = 0; t < 4; t++) {
                __half2 b3v = *(const __half2*)(g_b3h + t * 8 + cc);
                __half2 v0 = __hmax2(__hadd2(*(__half2*)&acc3[t][0], b3v), z);
                __half2 v1 = __hmax2(__hadd2(*(__half2*)&acc3[t][1], b3v), z);
                af2[t >> 1][(t & 1) * 2 + 0] = *(uint32_t*)&v0;
                af2[t >> 1][(t & 1) * 2 + 1] = *(uint32_t*)&v1;
            }

            // ---- L4 (f16 acc): K=32, N=32 ----
            uint32_t acc4[4][2];
#pragma unroll
            for (int t = 0; t < 4; t++) { acc4[t][0] = 0u; acc4[t][1] = 0u; }
            {
                uint32_t wA[2];
#pragma unroll
                for (int j = 0; j < 2; j++)
                    wA[j] = sbase + OFF_W4
                          + (uint32_t)((j * 2 + (lane >> 4)) * 8 + (lane & 7)) * 80u
                          + (uint32_t)(((lane >> 3) & 1) << 4);
#pragma unroll
                for (int ks = 0; ks < 2; ks++) {
#pragma unroll
                    for (int j = 0; j < 2; j++) {
                        uint32_t bw[4];
                        ldsm4(bw, wA[j] + ks * 32);
                        mma_f16acc(acc4[j * 2], af2[ks], &bw[0]);
                        mma_f16acc(acc4[j * 2 + 1], af2[ks], &bw[2]);
                    }
                }
            }

            // ---- L5 (regs): relu(+b4) . w5, quad reduce -> RED ----
            float s0 = 0.f, s1 = 0.f;
#pragma unroll
            for (int t = 0; t < 4; t++) {
                __half2 b4v = *(const __half2*)(g_b4h + t * 8 + cc);
                __half2 h0 = __hmax2(__hadd2(*(__half2*)&acc4[t][0], b4v), z);
                __half2 h1 = __hmax2(__hadd2(*(__half2*)&acc4[t][1], b4v), z);
                float2 f0 = __half22float2(h0);
                float2 f1 = __half22float2(h1);
                float wx = misc[MISC_W5 + t * 8 + cc], wy = misc[MISC_W5 + t * 8 + cc + 1];
                s0 += f0.x * wx + f0.y * wy;
                s1 += f1.x * wx + f1.y * wy;
            }
            s0 += __shfl_xor_sync(0xffffffffu, s0, 1);
            s0 += __shfl_xor_sync(0xffffffffu, s0, 2);
            s1 += __shfl_xor_sync(0xffffffffu, s1, 1);
            s1 += __shfl_xor_sync(0xffffffffu, s1, 2);
            if ((lane & 3) == 0) {
                int row = weff * 16 + r;
                misc[MISC_RED + row] = s0;
                misc[MISC_RED + row + 8] = s1;
            }
        }
        __syncthreads();   // RED partials done

        if (tid < 100) {
            float s = misc[MISC_RED + tid] + misc[MISC_B5];
            misc[MISC_RED + tid] = 1.f / (1.f + __expf(-s));
        }
        __syncthreads();
        if (tid < 32) {
            float v = misc[MISC_RED + tid] + misc[MISC_RED + tid + 32]
                    + misc[MISC_RED + tid + 64]
                    + ((tid < 4) ? misc[MISC_RED + tid + 96] : 0.f);
#pragma unroll
            for (int off = 16; off; off >>= 1)
                v += __shfl_down_sync(0xffffffffu, v, off);
            if (tid == 0) out[b] = v * (1.f / 100.f);
        }
        // next iteration's nidx-write sync orders everything
    }
}

// ---------------------------------------------------------------------------
extern "C" void kernel_launch(void* const* d_in, const int* in_sizes, int n_in,
                              void* d_out, int out_size)
{
    const float* user_emb = (const float*)d_in[0];
    const float* item_emb = (const float*)d_in[1];
    const float* user_scr = (const float*)d_in[2];
    const float* item_scr = (const float*)d_in[3];
    const float* w1 = (const float*)d_in[4];
    const float* b1 = (const float*)d_in[5];
    const float* w2 = (const float*)d_in[6];
    const float* b2 = (const float*)d_in[7];
    const float* w3 = (const float*)d_in[8];
    const float* b3 = (const float*)d_in[9];
    const float* w4 = (const float*)d_in[10];
    const float* b4 = (const float*)d_in[11];
    const float* w5 = (const float*)d_in[12];
    const float* b5 = (const float*)d_in[13];
    const int* user_idx_tensor = (const int*)d_in[14];
    const int* item_idx_tensor = (const int*)d_in[15];
    const int* user_idxs = (const int*)d_in[16];
    const int* item_idxs = (const int*)d_in[17];
    float* out = (float*)d_out;

    scrpre_kernel<<<SCRPRE_BLOCKS, 256>>>(user_scr, item_scr,
                                          w2, w3, w4, b2, b3, b4);
    pe_kernel<<<PE_BLOCKS, 256>>>(user_emb, item_emb, w1);

    cudaFuncSetAttribute(cnn_main_kernel,
                         cudaFuncAttributeMaxDynamicSharedMemorySize, SMEM_BYTES);
    cnn_main_kernel<<<PERSIST_GRID, 256, SMEM_BYTES>>>(
        b1, w5, b5,
        user_idx_tensor, item_idx_tensor, user_idxs, item_idxs,
        out);
}

// round 17
// speedup vs baseline: 1.1362x; 1.1362x over previous
#include <cuda_runtime.h>
#include <cuda_fp16.h>
#include <math.h>
#include <stdint.h>

#define NU 100000
#define NI 50000
#define KN 100
#define BB 8192

// Precomputed fp16 tables
__device__ __half g_pe_user[NU * 64];
__device__ __half g_pe_item[NI * 64];
__device__ __half g_uscr16[(size_t)NU * 112];
__device__ __half g_iscr16[(size_t)NI * 112];
__device__ __half g_w2h[64 * 64];
__device__ __half g_w3h[32 * 64];
__device__ __half g_w4h[32 * 32];
__device__ __half g_b2h[64];
__device__ __half g_b3h[32];
__device__ __half g_b4h[32];

// ---------------------------------------------------------------------------
// Main-kernel SMEM, 3 CTAs/SM. Activations never touch smem (register chain).
//   ABUF [112 r][120 kh] stride 240B @ 0 (26880)
//   B1  [224 k][64 nh] stride 128B XOR-swizzled @ 26880 (28672)
//   W2 [64][72h] stride 144 @ 55552 (9216)
//   W3 [32][72h] stride 144 @ 64768 (4608)
//   W4 [32][40h] stride 80  @ 69376 (2560)
//   MISC (floats)           @ 71936
// ---------------------------------------------------------------------------
#define OFF_AB   0
#define OFF_B1   26880
#define OFF_W2   55552
#define OFF_W3   64768
#define OFF_W4   69376
#define OFF_MISC 71936
#define SMEM_BYTES 73792
#define MISC_W5   0
#define MISC_B5   32
#define MISC_RED  36
#define MISC_NIDX 152

#define CP_ASYNC16(dst, src) \
    asm volatile("cp.async.cg.shared.global [%0], [%1], 16;" :: "r"(dst), "l"(src))
#define CP_COMMIT() asm volatile("cp.async.commit_group;" ::: "memory")
#define CP_WAIT0()  asm volatile("cp.async.wait_group 0;" ::: "memory")

__device__ __forceinline__ void ldsm4(uint32_t (&r)[4], uint32_t a) {
    asm volatile("ldmatrix.sync.aligned.m8n8.x4.shared.b16 {%0,%1,%2,%3}, [%4];"
                 : "=r"(r[0]), "=r"(r[1]), "=r"(r[2]), "=r"(r[3]) : "r"(a));
}
__device__ __forceinline__ void ldsm2(uint32_t (&r)[2], uint32_t a) {
    asm volatile("ldmatrix.sync.aligned.m8n8.x2.shared.b16 {%0,%1}, [%2];"
                 : "=r"(r[0]), "=r"(r[1]) : "r"(a));
}
__device__ __forceinline__ void ldsm4t(uint32_t (&r)[4], uint32_t a) {
    asm volatile("ldmatrix.sync.aligned.m8n8.x4.trans.shared.b16 {%0,%1,%2,%3}, [%4];"
                 : "=r"(r[0]), "=r"(r[1]), "=r"(r[2]), "=r"(r[3]) : "r"(a));
}
__device__ __forceinline__ void mma_f32acc(float (&c)[4], const uint32_t* a,
                                           const uint32_t* b) {
    asm volatile(
        "mma.sync.aligned.m16n8k16.row.col.f32.f16.f16.f32 "
        "{%0,%1,%2,%3}, {%4,%5,%6,%7}, {%8,%9}, {%0,%1,%2,%3};"
        : "+f"(c[0]), "+f"(c[1]), "+f"(c[2]), "+f"(c[3])
        : "r"(a[0]), "r"(a[1]), "r"(a[2]), "r"(a[3]), "r"(b[0]), "r"(b[1]));
}
__device__ __forceinline__ void mma_f16acc(uint32_t (&c)[2], const uint32_t* a,
                                           const uint32_t* b) {
    asm volatile(
        "mma.sync.aligned.m16n8k16.row.col.f16.f16.f16.f16 "
        "{%0,%1}, {%2,%3,%4,%5}, {%6,%7}, {%0,%1};"
        : "+r"(c[0]), "+r"(c[1])
        : "r"(a[0]), "r"(a[1]), "r"(a[2]), "r"(a[3]), "r"(b[0]), "r"(b[1]));
}

__device__ __forceinline__ uint32_t h2_bits(float x, float y) {
    __half2 h = __floats2half2_rn(x, y);
    return *(uint32_t*)&h;
}
__device__ __forceinline__ void cvt_store4(char* dst, float4 v) {
    uint32_t lo = h2_bits(v.x, v.y), hi = h2_bits(v.z, v.w);
    uint2 u; u.x = lo; u.y = hi;
    *(uint2*)dst = u;
}

// ---------------------------------------------------------------------------
// scrpre_kernel (NO smem -> full occupancy): scr u/i conversion + wcvt
// ---------------------------------------------------------------------------
#define SCRU_BLK ((NU * 14 + 255) / 256)
#define SCRI_BLK ((NI * 14 + 255) / 256)
#define WCVT_BLK 29
#define SCRPRE_BLOCKS (SCRU_BLK + SCRI_BLK + WCVT_BLK)

__device__ __forceinline__ void scr_chunk(
    const float* __restrict__ src, __half* __restrict__ dst, int nrows, int t)
{
    if (t >= nrows * 14) return;
    int n = t / 14, cb = t % 14;
    uint32_t o[4] = {0, 0, 0, 0};
    if (cb < 12) {
        float4 a = *(const float4*)(src + (size_t)n * 100 + cb * 8);
        float4 bq = *(const float4*)(src + (size_t)n * 100 + cb * 8 + 4);
        o[0] = h2_bits(a.x, a.y);  o[1] = h2_bits(a.z, a.w);
        o[2] = h2_bits(bq.x, bq.y); o[3] = h2_bits(bq.z, bq.w);
    } else if (cb == 12) {
        float4 a = *(const float4*)(src + (size_t)n * 100 + 96);
        o[0] = h2_bits(a.x, a.y);  o[1] = h2_bits(a.z, a.w);
    }
    uint4 v; v.x = o[0]; v.y = o[1]; v.z = o[2]; v.w = o[3];
    *(uint4*)(dst + (size_t)n * 112 + cb * 8) = v;
}

__global__ __launch_bounds__(256) void scrpre_kernel(
    const float* __restrict__ user_scr, const float* __restrict__ item_scr,
    const float* __restrict__ w2, const float* __restrict__ w3,
    const float* __restrict__ w4, const float* __restrict__ b2,
    const float* __restrict__ b3, const float* __restrict__ b4)
{
    const int bid = blockIdx.x, tid = threadIdx.x;
    if (bid < SCRU_BLK) {
        scr_chunk(user_scr, g_uscr16, NU, bid * 256 + tid);
    } else if (bid < SCRU_BLK + SCRI_BLK) {
        scr_chunk(item_scr, g_iscr16, NI, (bid - SCRU_BLK) * 256 + tid);
    } else {
        int t = (bid - SCRU_BLK - SCRI_BLK) * 256 + tid;
        if (t < 4096) g_w2h[t] = __float2half_rn(w2[t]);
        else if (t < 6144) g_w3h[t - 4096] = __float2half_rn(w3[t - 4096]);
        else if (t < 7168) g_w4h[t - 6144] = __float2half_rn(w4[t - 6144]);
        else if (t < 7232) g_b2h[t - 7168] = __float2half_rn(b2[t - 7168]);
        else if (t < 7264) g_b3h[t - 7232] = __float2half_rn(b3[t - 7232]);
        else if (t < 7296) g_b4h[t - 7264] = __float2half_rn(b4[t - 7264]);
    }
}

// ---------------------------------------------------------------------------
// pe_kernel (smem; separate launch)
// ---------------------------------------------------------------------------
#define PEU_BLOCKS  ((NU + 255) / 256)
#define PEI_BLOCKS  ((NI + 255) / 256)
#define PE_BLOCKS   (PEU_BLOCKS + PEI_BLOCKS)

__device__ __forceinline__ void pe_block(
    const float* __restrict__ emb, const float* __restrict__ w1,
    int w1_off, __half* __restrict__ pe, int nrows, int rows0,
    __half* W1h, __half* E, int tid)
{
    for (int t = tid; t < 64 * 16; t += 256) {
        int o = t >> 4, k4 = t & 15;
        float4 v = *(const float4*)(w1 + o * 128 + w1_off + k4 * 4);
        cvt_store4((char*)(W1h + o * 72 + k4 * 4), v);
    }
    for (int t = tid; t < 256 * 16; t += 256) {
        int r = t >> 4, k4 = t & 15;
        int n = rows0 + r;
        float4 v = (n < nrows) ? *(const float4*)(emb + (size_t)n * 64 + k4 * 4)
                               : make_float4(0.f, 0.f, 0.f, 0.f);
        cvt_store4((char*)(E + r * 72 + k4 * 4), v);
    }
    __syncthreads();

    const int lane = tid & 31, w = tid >> 5;
    uint32_t sE = (uint32_t)__cvta_generic_to_shared(E);
    uint32_t sW = (uint32_t)__cvta_generic_to_shared(W1h);
    uint32_t aAddr[2];
#pragma unroll
    for (int mt = 0; mt < 2; mt++)
        aAddr[mt] = sE + (uint32_t)(w * 32 + mt * 16 + (lane & 15)) * 144u
                  + (uint32_t)((lane >> 4) << 4);
    uint32_t bAddr0 = sW + (uint32_t)(lane & 7) * 144u + (uint32_t)(((lane >> 3) & 1) << 4);

    float acc[2][8][4];
#pragma unroll
    for (int mt = 0; mt < 2; mt++)
#pragma unroll
        for (int nt = 0; nt < 8; nt++)
#pragma unroll
            for (int i = 0; i < 4; i++) acc[mt][nt][i] = 0.f;

#pragma unroll
    for (int ks = 0; ks < 4; ks++) {
        uint32_t a[2][4];
        ldsm4(a[0], aAddr[0] + ks * 32);
        ldsm4(a[1], aAddr[1] + ks * 32);
#pragma unroll
        for (int nt = 0; nt < 8; nt++) {
            uint32_t b[2];
            ldsm2(b, bAddr0 + (uint32_t)nt * 8u * 144u + ks * 32);
            mma_f32acc(acc[0][nt], a[0], b);
            mma_f32acc(acc[1][nt], a[1], b);
        }
    }

    int c0 = (lane & 3) * 2;
#pragma unroll
    for (int mt = 0; mt < 2; mt++) {
        int r0 = rows0 + w * 32 + mt * 16 + (lane >> 2);
#pragma unroll
        for (int nt = 0; nt < 8; nt++) {
            int col = nt * 8 + c0;
            if (r0 < nrows)
                *(__half2*)(pe + (size_t)r0 * 64 + col) =
                    __floats2half2_rn(acc[mt][nt][0], acc[mt][nt][1]);
            if (r0 + 8 < nrows)
                *(__half2*)(pe + (size_t)(r0 + 8) * 64 + col) =
                    __floats2half2_rn(acc[mt][nt][2], acc[mt][nt][3]);
        }
    }
}

__global__ __launch_bounds__(256) void pe_kernel(
    const float* __restrict__ user_emb, const float* __restrict__ item_emb,
    const float* __restrict__ w1)
{
    __shared__ __half W1h[64 * 72];
    __shared__ __half E[256 * 72];
    const int bid = blockIdx.x, tid = threadIdx.x;
    if (bid < PEU_BLOCKS)
        pe_block(user_emb, w1, 0, g_pe_user, NU, bid * 256, W1h, E, tid);
    else
        pe_block(item_emb, w1, 64, g_pe_item, NI, (bid - PEU_BLOCKS) * 256, W1h, E, tid);
}

// ---------------------------------------------------------------------------
// Main kernel (non-persistent, R15 structure): warp weff (0-6) owns rows
// 16*weff..+15; MLP chain after GEMM1 in registers. The item-half ABUF
// reload is interleaved into GEMM1 pass 1 (chunks become dead per k-step),
// hiding the reload's global-load latency behind pass-1 compute.
// ---------------------------------------------------------------------------
__global__ __launch_bounds__(256, 3) void cnn_main_kernel(
    const float* __restrict__ b1g,
    const float* __restrict__ w5g, const float* __restrict__ b5g,
    const int* __restrict__ uidxT, const int* __restrict__ iidxT,
    const int* __restrict__ uidxs, const int* __restrict__ iidxs,
    float* __restrict__ out)
{
    extern __shared__ char smb[];
    float* misc = (float*)(smb + OFF_MISC);
    int* nidx = (int*)(misc + MISC_NIDX);
    uint32_t sbase = (uint32_t)__cvta_generic_to_shared(smb);
    const int tid = threadIdx.x;
    const int b = blockIdx.x;

    // Phase 0
    if (tid < 200) {
        nidx[tid] = (tid < 100) ? uidxT[(size_t)uidxs[b] * KN + tid]
                                : iidxT[(size_t)iidxs[b] * KN + (tid - 100)];
    } else if (tid < 232) {
        misc[MISC_W5 + tid - 200] = w5g[tid - 200];
    } else if (tid == 232) {
        misc[MISC_B5] = b5g[0];
    }
    if (tid < 192) {
        int rr = tid >> 3;
        int row = (rr < 12) ? 100 + rr : 200 + rr;
        *(uint4*)(smb + OFF_B1 + row * 128 + (tid & 7) * 16) = make_uint4(0, 0, 0, 0);
    }
    __syncthreads();

    // Phase 1: gathers (all 8 warps)
    for (int t = tid; t < 1400; t += 256) {
        int r = t / 14, c = t % 14;
        CP_ASYNC16(sbase + OFF_AB + (uint32_t)(r * 240 + c * 16),
                   (const char*)(g_uscr16 + (size_t)nidx[r] * 112) + c * 16);
    }
    for (int t = tid; t < 1600; t += 256) {
        int j = t >> 3, c = t & 7;
        const char* src = (j < 100)
            ? (const char*)(g_pe_user + (size_t)nidx[j] * 64) + c * 16
            : (const char*)(g_pe_item + (size_t)nidx[j] * 64) + c * 16;
        int dr = (j < 100) ? j : j + 12;
        CP_ASYNC16(sbase + OFF_B1 + (uint32_t)(dr * 128 + ((c ^ (dr & 7)) << 4)), src);
    }
    for (int t = tid; t < 512; t += 256) {
        int o = t >> 3, c = t & 7;
        CP_ASYNC16(sbase + OFF_W2 + (uint32_t)(o * 144 + c * 16),
                   (const char*)(g_w2h + o * 64 + c * 8));
    }
    if (tid < 256) {
        int o = tid >> 3, c = tid & 7;
        CP_ASYNC16(sbase + OFF_W3 + (uint32_t)(o * 144 + c * 16),
                   (const char*)(g_w3h + o * 64 + c * 8));
    }
    if (tid < 128) {
        int o = tid >> 2, c = tid & 3;
        CP_ASYNC16(sbase + OFF_W4 + (uint32_t)(o * 80 + c * 16),
                   (const char*)(g_w4h + o * 32 + c * 8));
    }
    CP_COMMIT();
    CP_WAIT0();
    __syncthreads();   // block sync #1: all tiles resident

    const int lane = tid & 31, w = tid >> 5;
    const int weff = (w + b) & 7;    // rotate idle warp per batch element
    const int cc = (lane & 3) * 2;
    const int r = lane >> 2;

    if (weff < 7) {
        // ---- GEMM1 (fp32 acc): rows 16*weff.., 8 n-tiles, K=224 (2x7)
        float acc1[8][4];
#pragma unroll
        for (int t = 0; t < 8; t++)
#pragma unroll
            for (int i = 0; i < 4; i++) acc1[t][i] = 0.f;

        uint32_t aAddr = sbase + OFF_AB
                       + (uint32_t)(weff * 16 + (lane & 15)) * 240u
                       + (uint32_t)((lane >> 4) << 4);
        uint32_t bAddr[4];
#pragma unroll
        for (int j = 0; j < 4; j++)
            bAddr[j] = sbase + OFF_B1 + (uint32_t)(lane & 15) * 128u
                     + (uint32_t)((((j * 2 + (lane >> 4)) ^ (lane & 7)) & 7) << 4);

        // interleaved reload coords: this lane refills chunk 2ks+(lane>>4) of
        // its row right after pass-1's ldsm4 for step ks has consumed it
        const int rl_row = weff * 16 + (lane & 15);
        const char* isrc = (rl_row < 100)
            ? (const char*)(g_iscr16 + (size_t)nidx[100 + rl_row] * 112)
            : (const char*)(g_iscr16);   // dummy (guarded below)
        uint32_t rdst = sbase + OFF_AB + (uint32_t)rl_row * 240u
                      + (uint32_t)((lane >> 4) << 4);

#pragma unroll
        for (int ks = 0; ks < 7; ks++) {
            uint32_t a[4];
            ldsm4(a, aAddr + ks * 32);
            // refill the just-consumed chunks with the item half
            if (rl_row < 100) {
                int ch = ks * 2;   // + (lane>>4) folded into rdst/isrc offsets
                CP_ASYNC16(rdst + ch * 16, isrc + ch * 16 + ((lane >> 4) << 4));
            }
#pragma unroll
            for (int j = 0; j < 4; j++) {
                uint32_t bq[4];
                ldsm4t(bq, bAddr[j] + ks * 2048);
                mma_f32acc(acc1[j * 2], a, &bq[0]);
                mma_f32acc(acc1[j * 2 + 1], a, &bq[2]);
            }
        }
        CP_COMMIT();
        CP_WAIT0();
        __syncwarp();

#pragma unroll
        for (int ks = 0; ks < 7; ks++) {
            uint32_t a[4];
            ldsm4(a, aAddr + ks * 32);
#pragma unroll
            for (int j = 0; j < 4; j++) {
                uint32_t bq[4];
                ldsm4t(bq, bAddr[j] + 14336 + ks * 2048);
                mma_f32acc(acc1[j * 2], a, &bq[0]);
                mma_f32acc(acc1[j * 2 + 1], a, &bq[2]);
            }
        }

        // Epilogue 1 (regs): relu(+b1) -> L2 A-fragments
        uint32_t af[4][4];
#pragma unroll
        for (int t = 0; t < 8; t++) {
            float2 bf = *(const float2*)(b1g + t * 8 + cc);
            uint32_t u0 = h2_bits(fmaxf(acc1[t][0] + bf.x, 0.f),
                                  fmaxf(acc1[t][1] + bf.y, 0.f));
            uint32_t u1 = h2_bits(fmaxf(acc1[t][2] + bf.x, 0.f),
                                  fmaxf(acc1[t][3] + bf.y, 0.f));
            af[t >> 1][(t & 1) * 2 + 0] = u0;
            af[t >> 1][(t & 1) * 2 + 1] = u1;
        }

        const __half2 z = __floats2half2_rn(0.f, 0.f);

        // ---- L2 (f16 acc): K=64, N=64, A in regs ----
        uint32_t acc2[8][2];
#pragma unroll
        for (int t = 0; t < 8; t++) { acc2[t][0] = 0u; acc2[t][1] = 0u; }
        {
            uint32_t wA[4];
#pragma unroll
            for (int j = 0; j < 4; j++)
                wA[j] = sbase + OFF_W2
                      + (uint32_t)((j * 2 + (lane >> 4)) * 8 + (lane & 7)) * 144u
                      + (uint32_t)(((lane >> 3) & 1) << 4);
#pragma unroll
            for (int ks = 0; ks < 4; ks++) {
#pragma unroll
                for (int j = 0; j < 4; j++) {
                    uint32_t bw[4];
                    ldsm4(bw, wA[j] + ks * 32);
                    mma_f16acc(acc2[j * 2], af[ks], &bw[0]);
                    mma_f16acc(acc2[j * 2 + 1], af[ks], &bw[2]);
                }
            }
        }
        // Epilogue 2 (regs): relu(+b2) -> L3 A-frags (reuse af)
        uint32_t af2[2][4];
#pragma unroll
        for (int t = 0; t < 8; t++) {
            __half2 b2v = *(const __half2*)(g_b2h + t * 8 + cc);
            __half2 v0 = __hmax2(__hadd2(*(__half2*)&acc2[t][0], b2v), z);
            __half2 v1 = __hmax2(__hadd2(*(__half2*)&acc2[t][1], b2v), z);
            af[t >> 1][(t & 1) * 2 + 0] = *(uint32_t*)&v0;
            af[t >> 1][(t & 1) * 2 + 1] = *(uint32_t*)&v1;
        }

        // ---- L3 (f16 acc): K=64, N=32 ----
        uint32_t acc3[4][2];
#pragma unroll
        for (int t = 0; t < 4; t++) { acc3[t][0] = 0u; acc3[t][1] = 0u; }
        {
            uint32_t wA[2];
#pragma unroll
            for (int j = 0; j < 2; j++)
                wA[j] = sbase + OFF_W3
                      + (uint32_t)((j * 2 + (lane >> 4)) * 8 + (lane & 7)) * 144u
                      + (uint32_t)(((lane >> 3) & 1) << 4);
#pragma unroll
            for (int ks = 0; ks < 4; ks++) {
#pragma unroll
                for (int j = 0; j < 2; j++) {
                    uint32_t bw[4];
                    ldsm4(bw, wA[j] + ks * 32);
                    mma_f16acc(acc3[j * 2], af[ks], &bw[0]);
                    mma_f16acc(acc3[j * 2 + 1], af[ks], &bw[2]);
                }
            }
        }
        // Epilogue 3 (regs): relu(+b3) -> L4 A-frags
#pragma unroll
        for (int t = 0; t < 4; t++) {
            __half2 b3v = *(const __half2*)(g_b3h + t * 8 + cc);
            __half2 v0 = __hmax2(__hadd2(*(__half2*)&acc3[t][0], b3v), z);
            __half2 v1 = __hmax2(__hadd2(*(__half2*)&acc3[t][1], b3v), z);
            af2[t >> 1][(t & 1) * 2 + 0] = *(uint32_t*)&v0;
            af2[t >> 1][(t & 1) * 2 + 1] = *(uint32_t*)&v1;
        }

        // ---- L4 (f16 acc): K=32, N=32 ----
        uint32_t acc4[4][2];
#pragma unroll
        for (int t = 0; t < 4; t++) { acc4[t][0] = 0u; acc4[t][1] = 0u; }
        {
            uint32_t wA[2];
#pragma unroll
            for (int j = 0; j < 2; j++)
                wA[j] = sbase + OFF_W4
                      + (uint32_t)((j * 2 + (lane >> 4)) * 8 + (lane & 7)) * 80u
                      + (uint32_t)(((lane >> 3) & 1) << 4);
#pragma unroll
            for (int ks = 0; ks < 2; ks++) {
#pragma unroll
                for (int j = 0; j < 2; j++) {
                    uint32_t bw[4];
                    ldsm4(bw, wA[j] + ks * 32);
                    mma_f16acc(acc4[j * 2], af2[ks], &bw[0]);
                    mma_f16acc(acc4[j * 2 + 1], af2[ks], &bw[2]);
                }
            }
        }

        // ---- L5 (regs): relu(+b4) . w5, quad reduce -> RED ----
        float s0 = 0.f, s1 = 0.f;
#pragma unroll
        for (int t = 0; t < 4; t++) {
            __half2 b4v = *(const __half2*)(g_b4h + t * 8 + cc);
            __half2 h0 = __hmax2(__hadd2(*(__half2*)&acc4[t][0], b4v), z);
            __half2 h1 = __hmax2(__hadd2(*(__half2*)&acc4[t][1], b4v), z);
            float2 f0 = __half22float2(h0);
            float2 f1 = __half22float2(h1);
            float wx = misc[MISC_W5 + t * 8 + cc], wy = misc[MISC_W5 + t * 8 + cc + 1];
            s0 += f0.x * wx + f0.y * wy;
            s1 += f1.x * wx + f1.y * wy;
        }
        s0 += __shfl_xor_sync(0xffffffffu, s0, 1);
        s0 += __shfl_xor_sync(0xffffffffu, s0, 2);
        s1 += __shfl_xor_sync(0xffffffffu, s1, 1);
        s1 += __shfl_xor_sync(0xffffffffu, s1, 2);
        if ((lane & 3) == 0) {
            int row = weff * 16 + r;
            misc[MISC_RED + row] = s0;
            misc[MISC_RED + row + 8] = s1;
        }
    }
    __syncthreads();   // block sync #2: RED partials done

    if (tid < 100) {
        float s = misc[MISC_RED + tid] + misc[MISC_B5];
        misc[MISC_RED + tid] = 1.f / (1.f + __expf(-s));
    }
    __syncthreads();
    if (tid < 32) {
        float v = misc[MISC_RED + tid] + misc[MISC_RED + tid + 32]
                + misc[MISC_RED + tid + 64]
                + ((tid < 4) ? misc[MISC_RED + tid + 96] : 0.f);
#pragma unroll
        for (int off = 16; off; off >>= 1)
            v += __shfl_down_sync(0xffffffffu, v, off);
        if (tid == 0) out[b] = v * (1.f / 100.f);
    }
}

// ---------------------------------------------------------------------------
extern "C" void kernel_launch(void* const* d_in, const int* in_sizes, int n_in,
                              void* d_out, int out_size)
{
    const float* user_emb = (const float*)d_in[0];
    const float* item_emb = (const float*)d_in[1];
    const float* user_scr = (const float*)d_in[2];
    const float* item_scr = (const float*)d_in[3];
    const float* w1 = (const float*)d_in[4];
    const float* b1 = (const float*)d_in[5];
    const float* w2 = (const float*)d_in[6];
    const float* b2 = (const float*)d_in[7];
    const float* w3 = (const float*)d_in[8];
    const float* b3 = (const float*)d_in[9];
    const float* w4 = (const float*)d_in[10];
    const float* b4 = (const float*)d_in[11];
    const float* w5 = (const float*)d_in[12];
    const float* b5 = (const float*)d_in[13];
    const int* user_idx_tensor = (const int*)d_in[14];
    const int* item_idx_tensor = (const int*)d_in[15];
    const int* user_idxs = (const int*)d_in[16];
    const int* item_idxs = (const int*)d_in[17];
    float* out = (float*)d_out;

    scrpre_kernel<<<SCRPRE_BLOCKS, 256>>>(user_scr, item_scr,
                                          w2, w3, w4, b2, b3, b4);
    pe_kernel<<<PE_BLOCKS, 256>>>(user_emb, item_emb, w1);

    cudaFuncSetAttribute(cnn_main_kernel,
                         cudaFuncAttributeMaxDynamicSharedMemorySize, SMEM_BYTES);
    cnn_main_kernel<<<BB, 256, SMEM_BYTES>>>(
        b1, w5, b5,
        user_idx_tensor, item_idx_tensor, user_idxs, item_idxs,
        out);
}